// round 6
// baseline (speedup 1.0000x reference)
#include <cuda_runtime.h>
#include <math.h>
#include <stdint.h>

#define DIM 128
#define NL 50000
#define NP 100000
#define ELL 500000
#define EPP 400000
#define ELP 500000
#define EPL 500000

// ---------------- scratch (device globals; allocation-free rule) ----------------
__device__ __align__(16) float g_xL[NL * DIM];
__device__ __align__(16) float g_xP[NP * DIM];
__device__ __align__(16) float g_legoA[NL * DIM];
__device__ __align__(16) float g_pointA[NP * DIM];
__device__ __align__(16) float g_hs[NP * DIM];
__device__ __align__(16) float g_A512[NP * 512];   // aliased as qkvs[NL*512] (disjoint lifetimes)
__device__ __align__(16) float g_B512[NP * 512];
__device__ __align__(16) float g_Wt1c[512 * 128];
__device__ __align__(16) float g_Wt1b[512 * 128];
__device__ __align__(16) float g_W2t[128 * 512];
__device__ __align__(16) float g_Wt4[512 * 128];
__device__ __align__(16) float g_b4[512];
__device__ __align__(16) float g_WtG[128 * 128];
__device__ __align__(16) float g_esc[500000];
__device__ __align__(16) float g_nmax[NP];
__device__ __align__(16) float g_nsum[NP];
__device__ __align__(16) float g_ssrc[NP];
__device__ __align__(16) float g_sdst[NP];
__device__ __align__(16) float g_waD[DIM];
// sorted edge lists (built once per launch)
__device__ int g_ll_s[ELL], g_ll_d[ELL];
__device__ int g_pp_s[EPP], g_pp_d[EPP];
__device__ int g_lp_s[ELP], g_lp_d[ELP];
__device__ int g_pl_s[EPL], g_pl_d[EPL];
__device__ int g_cnt[NP];
__device__ int g_offs[NP];

// ---------------- small device helpers ----------------
__device__ __forceinline__ void atomicMaxF(float* a, float v) {
    if (v >= 0.f) atomicMax((int*)a, __float_as_int(v));
    else          atomicMin((unsigned int*)a, __float_as_uint(v));
}
__device__ __forceinline__ uint32_t to_tf32(float x) {
    uint32_t r;
    asm("cvt.rna.tf32.f32 %0, %1;" : "=r"(r) : "f"(x));
    return r;
}
__device__ __forceinline__ void ldsm4(uint32_t& r0, uint32_t& r1, uint32_t& r2, uint32_t& r3, uint32_t addr) {
    asm volatile("ldmatrix.sync.aligned.m8n8.x4.shared.b16 {%0,%1,%2,%3}, [%4];"
                 : "=r"(r0), "=r"(r1), "=r"(r2), "=r"(r3) : "r"(addr));
}
__device__ __forceinline__ void mma_tf32(float* c, const uint32_t* a, uint32_t b0, uint32_t b1) {
    asm volatile("mma.sync.aligned.m16n8k8.row.col.f32.tf32.tf32.f32 "
                 "{%0,%1,%2,%3},{%4,%5,%6,%7},{%8,%9},{%0,%1,%2,%3};"
                 : "+f"(c[0]), "+f"(c[1]), "+f"(c[2]), "+f"(c[3])
                 : "r"(a[0]), "r"(a[1]), "r"(a[2]), "r"(a[3]), "r"(b0), "r"(b1));
}
__device__ __forceinline__ void cp_async16(uint32_t saddr, const void* gaddr) {
    asm volatile("cp.async.cg.shared.global [%0], [%1], 16;" :: "r"(saddr), "l"(gaddr));
}
__device__ __forceinline__ void cp_commit() { asm volatile("cp.async.commit_group;"); }
__device__ __forceinline__ void cp_wait1() { asm volatile("cp.async.wait_group 1;" ::: "memory"); }
__device__ __forceinline__ void cp_wait0() { asm volatile("cp.async.wait_group 0;" ::: "memory"); }
__device__ __forceinline__ void red_add_v4(float* p, float4 v) {
    asm volatile("red.global.add.v4.f32 [%0], {%1,%2,%3,%4};"
                 :: "l"(p), "f"(v.x), "f"(v.y), "f"(v.z), "f"(v.w) : "memory");
}
__device__ __forceinline__ uint32_t sw_addr(uint32_t base, int r, int g) {
    return base + (uint32_t)((r * 32 + (((g) ^ (r & 7)) << 2)) * 4);
}

// ---------------- edge counting-sort by dst ----------------
__global__ void zero_int(int* __restrict__ p, int n) {
    int i = blockIdx.x * blockDim.x + threadIdx.x;
    if (i < n) p[i] = 0;
}
__global__ void histo_k(const int* __restrict__ dst, int E, int* __restrict__ cnt) {
    int e = blockIdx.x * blockDim.x + threadIdx.x;
    if (e < E) atomicAdd(&cnt[dst[e]], 1);
}
// Single-block 2-level exclusive scan: cnt[0..n) -> offs[0..n)
__global__ __launch_bounds__(1024) void exscan_k(const int* __restrict__ cnt, int n, int* __restrict__ offs) {
    __shared__ int part[1024];
    int t = threadIdx.x;
    int chunk = (n + 1023) / 1024;
    int begin = t * chunk;
    int end = begin + chunk; if (end > n) end = n; if (begin > n) begin = n;
    int s = 0;
    for (int i = begin; i < end; i++) s += cnt[i];
    part[t] = s;
    __syncthreads();
    for (int off = 1; off < 1024; off <<= 1) {
        int v = (t >= off) ? part[t - off] : 0;
        __syncthreads();
        part[t] += v;
        __syncthreads();
    }
    int base = (t == 0) ? 0 : part[t - 1];
    for (int i = begin; i < end; i++) { offs[i] = base; base += cnt[i]; }
}
__global__ void sortscat_k(const int* __restrict__ src, const int* __restrict__ dst, int E,
                           int* __restrict__ offs, int* __restrict__ ss, int* __restrict__ sd) {
    int e = blockIdx.x * blockDim.x + threadIdx.x;
    if (e >= E) return;
    int d = dst[e];
    int p = atomicAdd(&offs[d], 1);
    ss[p] = src[e];
    sd[p] = d;
}

// ---------------- 3xTF32 pipelined node GEMM (fp32-accurate) ----------------
__global__ __launch_bounds__(256) void gemm_3xtf32_pipe(
    const float* __restrict__ X, const float* __restrict__ Wt,
    const float* __restrict__ bias, float* __restrict__ C, int M, int N) {
    extern __shared__ __align__(16) float smemBuf[];
    uint32_t sBase = (uint32_t)__cvta_generic_to_shared(smemBuf);
    int t = threadIdx.x;
    int rowBase = blockIdx.x * 128;
    int colBase = blockIdx.y * 128;
    int warp = t >> 5, lane = t & 31;
    int wm = warp >> 2, wn = warp & 3;
    int mBase = wm * 64, nBase = wn * 32;
    int lr = lane & 15, lh = lane >> 4;

    auto prefetch = [&](int it) {
        int k0 = it * 32;
        uint32_t stg = sBase + (uint32_t)((it & 1) * 32768);
#pragma unroll
        for (int i = 0; i < 4; i++) {
            int c = t + i * 256;
            int r = c >> 3, g = c & 7;
            int row = rowBase + r; if (row >= M) row = M - 1;
            cp_async16(sw_addr(stg, r, g), X + (size_t)row * 128 + k0 + g * 4);
            cp_async16(sw_addr(stg + 16384, r, g), Wt + (size_t)(colBase + r) * 128 + k0 + g * 4);
        }
        cp_commit();
    };

    float acc[4][4][4];
#pragma unroll
    for (int a = 0; a < 4; a++)
#pragma unroll
        for (int b = 0; b < 4; b++)
#pragma unroll
            for (int c = 0; c < 4; c++) acc[a][b][c] = 0.f;

    prefetch(0);
    for (int it = 0; it < 4; it++) {
        if (it + 1 < 4) { prefetch(it + 1); cp_wait1(); } else { cp_wait0(); }
        __syncthreads();
        uint32_t stg = sBase + (uint32_t)((it & 1) * 32768);
#pragma unroll
        for (int ks = 0; ks < 4; ks++) {
            int g = ks * 2 + lh;
            uint32_t ah[4][4], al[4][4], bh[2][4], bl[2][4];
#pragma unroll
            for (int mt = 0; mt < 4; mt++) {
                int row = mBase + mt * 16 + lr;
                uint32_t r0, r1, r2, r3;
                ldsm4(r0, r1, r2, r3, sw_addr(stg, row, g));
                uint32_t raw[4] = {r0, r1, r2, r3};
#pragma unroll
                for (int j = 0; j < 4; j++) {
                    float f = __uint_as_float(raw[j]);
                    uint32_t hi = to_tf32(f);
                    ah[mt][j] = hi;
                    al[mt][j] = to_tf32(f - __uint_as_float(hi));
                }
            }
#pragma unroll
            for (int p = 0; p < 2; p++) {
                int row = nBase + p * 16 + lr;
                uint32_t r0, r1, r2, r3;
                ldsm4(r0, r1, r2, r3, sw_addr(stg + 16384, row, g));
                uint32_t raw[4] = {r0, r1, r2, r3};
#pragma unroll
                for (int j = 0; j < 4; j++) {
                    float f = __uint_as_float(raw[j]);
                    uint32_t hi = to_tf32(f);
                    bh[p][j] = hi;
                    bl[p][j] = to_tf32(f - __uint_as_float(hi));
                }
            }
#pragma unroll
            for (int mt = 0; mt < 4; mt++)
#pragma unroll
                for (int nt = 0; nt < 4; nt++) {
                    int p = nt >> 1, wsel = nt & 1;
                    mma_tf32(acc[mt][nt], al[mt], bh[p][wsel], bh[p][2 + wsel]);
                    mma_tf32(acc[mt][nt], ah[mt], bl[p][wsel], bl[p][2 + wsel]);
                    mma_tf32(acc[mt][nt], ah[mt], bh[p][wsel], bh[p][2 + wsel]);
                }
        }
        __syncthreads();
    }
    int g = lane >> 2, tq = lane & 3;
#pragma unroll
    for (int mt = 0; mt < 4; mt++)
#pragma unroll
        for (int nt = 0; nt < 4; nt++) {
            int col = colBase + nBase + nt * 8 + tq * 2;
            float b0 = bias ? bias[col] : 0.f;
            float b1 = bias ? bias[col + 1] : 0.f;
            int row = rowBase + mBase + mt * 16 + g;
            if (row < M)
                *(float2*)&C[(size_t)row * N + col] = make_float2(acc[mt][nt][0] + b0, acc[mt][nt][1] + b1);
            row += 8;
            if (row < M)
                *(float2*)&C[(size_t)row * N + col] = make_float2(acc[mt][nt][2] + b0, acc[mt][nt][3] + b1);
        }
}

// ---------------- pipelined tf32 node GEMM (single-pass; edge path) ----------------
__global__ __launch_bounds__(256) void gemm_tf32_pipe(
    const float* __restrict__ X, const float* __restrict__ Wt,
    const float* __restrict__ bias, float* __restrict__ C, int M, int N) {
    extern __shared__ __align__(16) float smemBuf[];
    uint32_t sBase = (uint32_t)__cvta_generic_to_shared(smemBuf);
    int t = threadIdx.x;
    int rowBase = blockIdx.x * 128;
    int colBase = blockIdx.y * 128;
    int warp = t >> 5, lane = t & 31;
    int wm = warp >> 2, wn = warp & 3;
    int mBase = wm * 64, nBase = wn * 32;
    int lr = lane & 15, lh = lane >> 4;

    auto prefetch = [&](int it) {
        int k0 = it * 32;
        uint32_t stg = sBase + (uint32_t)((it & 1) * 32768);
#pragma unroll
        for (int i = 0; i < 4; i++) {
            int c = t + i * 256;
            int r = c >> 3, g = c & 7;
            int row = rowBase + r; if (row >= M) row = M - 1;
            cp_async16(sw_addr(stg, r, g), X + (size_t)row * 128 + k0 + g * 4);
            cp_async16(sw_addr(stg + 16384, r, g), Wt + (size_t)(colBase + r) * 128 + k0 + g * 4);
        }
        cp_commit();
    };

    float acc[4][4][4];
#pragma unroll
    for (int a = 0; a < 4; a++)
#pragma unroll
        for (int b = 0; b < 4; b++)
#pragma unroll
            for (int c = 0; c < 4; c++) acc[a][b][c] = 0.f;

    prefetch(0);
    for (int it = 0; it < 4; it++) {
        if (it + 1 < 4) { prefetch(it + 1); cp_wait1(); } else { cp_wait0(); }
        __syncthreads();
        uint32_t stg = sBase + (uint32_t)((it & 1) * 32768);
#pragma unroll
        for (int ks = 0; ks < 4; ks++) {
            int g = ks * 2 + lh;
            uint32_t a[4][4], b[2][4];
#pragma unroll
            for (int mt = 0; mt < 4; mt++) {
                int row = mBase + mt * 16 + lr;
                uint32_t r0, r1, r2, r3;
                ldsm4(r0, r1, r2, r3, sw_addr(stg, row, g));
                a[mt][0] = to_tf32(__uint_as_float(r0));
                a[mt][1] = to_tf32(__uint_as_float(r1));
                a[mt][2] = to_tf32(__uint_as_float(r2));
                a[mt][3] = to_tf32(__uint_as_float(r3));
            }
#pragma unroll
            for (int p = 0; p < 2; p++) {
                int row = nBase + p * 16 + lr;
                uint32_t r0, r1, r2, r3;
                ldsm4(r0, r1, r2, r3, sw_addr(stg + 16384, row, g));
                b[p][0] = to_tf32(__uint_as_float(r0));
                b[p][1] = to_tf32(__uint_as_float(r1));
                b[p][2] = to_tf32(__uint_as_float(r2));
                b[p][3] = to_tf32(__uint_as_float(r3));
            }
#pragma unroll
            for (int mt = 0; mt < 4; mt++)
#pragma unroll
                for (int nt = 0; nt < 4; nt++) {
                    int p = nt >> 1, wsel = nt & 1;
                    mma_tf32(acc[mt][nt], a[mt], b[p][wsel], b[p][2 + wsel]);
                }
        }
        __syncthreads();
    }
    int g = lane >> 2, tq = lane & 3;
#pragma unroll
    for (int mt = 0; mt < 4; mt++)
#pragma unroll
        for (int nt = 0; nt < 4; nt++) {
            int col = colBase + nBase + nt * 8 + tq * 2;
            float b0 = bias ? bias[col] : 0.f;
            float b1 = bias ? bias[col + 1] : 0.f;
            int row = rowBase + mBase + mt * 16 + g;
            if (row < M)
                *(float2*)&C[(size_t)row * N + col] = make_float2(acc[mt][nt][0] + b0, acc[mt][nt][1] + b1);
            row += 8;
            if (row < M)
                *(float2*)&C[(size_t)row * N + col] = make_float2(acc[mt][nt][2] + b0, acc[mt][nt][3] + b1);
        }
}

// ---------------- pipelined tf32 EdgeConv 2nd layer ----------------
__global__ __launch_bounds__(256) void edge_mlp2_tf32_pipe(
    const float* __restrict__ Ad, const float* __restrict__ Bs,
    const int* __restrict__ src, const int* __restrict__ dst,
    const float* __restrict__ W2t, const float* __restrict__ b2,
    float* __restrict__ out, int E) {
    extern __shared__ __align__(16) float smemBuf[];
    uint32_t sBase = (uint32_t)__cvta_generic_to_shared(smemBuf);
    __shared__ int sSrc[128], sDst[128];
    int t = threadIdx.x;
    int eBase = blockIdx.x * 128;
    if (t < 128) {
        int e = eBase + t; if (e >= E) e = E - 1;
        sSrc[t] = src[e]; sDst[t] = dst[e];
    }
    __syncthreads();
    int warp = t >> 5, lane = t & 31;
    int wm = warp >> 2, wn = warp & 3;
    int mBase = wm * 64, nBase = wn * 32;
    int lr = lane & 15, lh = lane >> 4;

    auto prefetch = [&](int it) {
        int k0 = it * 32;
        uint32_t stg = sBase + (uint32_t)((it & 1) * 49152);
#pragma unroll
        for (int i = 0; i < 4; i++) {
            int c = t + i * 256;
            int r = c >> 3, g = c & 7;
            uint32_t aAddr = sw_addr(stg, r, g);
            cp_async16(aAddr,         Ad  + (size_t)sDst[r] * 512 + k0 + g * 4);
            cp_async16(aAddr + 16384, Bs  + (size_t)sSrc[r] * 512 + k0 + g * 4);
            cp_async16(aAddr + 32768, W2t + (size_t)r * 512 + k0 + g * 4);
        }
        cp_commit();
    };

    float acc[4][4][4];
#pragma unroll
    for (int a = 0; a < 4; a++)
#pragma unroll
        for (int b = 0; b < 4; b++)
#pragma unroll
            for (int c = 0; c < 4; c++) acc[a][b][c] = 0.f;

    prefetch(0);
    for (int it = 0; it < 16; it++) {
        if (it + 1 < 16) { prefetch(it + 1); cp_wait1(); } else { cp_wait0(); }
        __syncthreads();
        uint32_t stg = sBase + (uint32_t)((it & 1) * 49152);
#pragma unroll
        for (int ks = 0; ks < 4; ks++) {
            int g = ks * 2 + lh;
            uint32_t a[4][4], b[2][4];
#pragma unroll
            for (int mt = 0; mt < 4; mt++) {
                int row = mBase + mt * 16 + lr;
                uint32_t addr = sw_addr(stg, row, g);
                uint32_t a0, a1, a2, a3, c0, c1, c2, c3;
                ldsm4(a0, a1, a2, a3, addr);
                ldsm4(c0, c1, c2, c3, addr + 16384);
                a[mt][0] = to_tf32(fmaxf(__uint_as_float(a0) + __uint_as_float(c0), 0.f));
                a[mt][1] = to_tf32(fmaxf(__uint_as_float(a1) + __uint_as_float(c1), 0.f));
                a[mt][2] = to_tf32(fmaxf(__uint_as_float(a2) + __uint_as_float(c2), 0.f));
                a[mt][3] = to_tf32(fmaxf(__uint_as_float(a3) + __uint_as_float(c3), 0.f));
            }
#pragma unroll
            for (int p = 0; p < 2; p++) {
                int row = nBase + p * 16 + lr;
                uint32_t r0, r1, r2, r3;
                ldsm4(r0, r1, r2, r3, sw_addr(stg + 32768, row, g));
                b[p][0] = to_tf32(__uint_as_float(r0));
                b[p][1] = to_tf32(__uint_as_float(r1));
                b[p][2] = to_tf32(__uint_as_float(r2));
                b[p][3] = to_tf32(__uint_as_float(r3));
            }
#pragma unroll
            for (int mt = 0; mt < 4; mt++)
#pragma unroll
                for (int nt = 0; nt < 4; nt++) {
                    int p = nt >> 1, wsel = nt & 1;
                    mma_tf32(acc[mt][nt], a[mt], b[p][wsel], b[p][2 + wsel]);
                }
        }
        __syncthreads();
    }
    int g = lane >> 2, tq = lane & 3;
#pragma unroll
    for (int mt = 0; mt < 4; mt++)
#pragma unroll
        for (int nt = 0; nt < 4; nt++) {
            int col = nBase + nt * 8 + tq * 2;
            float b0 = b2[col], b1 = b2[col + 1];
            int r = mBase + mt * 16 + g;
            if (eBase + r < E) {
                float* o = &out[(size_t)sDst[r] * 128 + col];
                atomicMaxF(o,     acc[mt][nt][0] + b0);
                atomicMaxF(o + 1, acc[mt][nt][1] + b1);
            }
            r += 8;
            if (eBase + r < E) {
                float* o = &out[(size_t)sDst[r] * 128 + col];
                atomicMaxF(o,     acc[mt][nt][2] + b0);
                atomicMaxF(o + 1, acc[mt][nt][3] + b1);
            }
        }
}

// ---------------- weight packing / transposes ----------------
__global__ void tr_w1(const float* __restrict__ W1, float* __restrict__ WtC, float* __restrict__ WtB) {
    __shared__ float tc[32][33], tb[32][33];
    int k0 = blockIdx.x * 32, n0 = blockIdx.y * 32;
    int tx = threadIdx.x, ty = threadIdx.y;
#pragma unroll
    for (int i = 0; i < 32; i += 8) {
        int k = k0 + ty + i, n = n0 + tx;
        float top = W1[k * 512 + n], bot = W1[(k + 128) * 512 + n];
        tc[ty + i][tx] = top - bot;
        tb[ty + i][tx] = bot;
    }
    __syncthreads();
#pragma unroll
    for (int i = 0; i < 32; i += 8) {
        int n = n0 + ty + i, k = k0 + tx;
        WtC[n * 128 + k] = tc[tx][ty + i];
        WtB[n * 128 + k] = tb[tx][ty + i];
    }
}
__global__ void tr_w2(const float* __restrict__ W2, float* __restrict__ W2t) {
    __shared__ float s[32][33];
    int k0 = blockIdx.x * 32, n0 = blockIdx.y * 32;
    int tx = threadIdx.x, ty = threadIdx.y;
#pragma unroll
    for (int i = 0; i < 32; i += 8)
        s[ty + i][tx] = W2[(k0 + ty + i) * 128 + n0 + tx];
    __syncthreads();
#pragma unroll
    for (int i = 0; i < 32; i += 8)
        W2t[(n0 + ty + i) * 512 + k0 + tx] = s[tx][ty + i];
}
__global__ void tr_pack4(const float* __restrict__ W0, const float* __restrict__ W1,
                         const float* __restrict__ W2, const float* __restrict__ W3,
                         float* __restrict__ Wt4) {
    __shared__ float s[32][33];
    int sel = blockIdx.z;
    const float* W = (sel == 0) ? W0 : (sel == 1) ? W1 : (sel == 2) ? W2 : W3;
    int k0 = blockIdx.x * 32, n0 = blockIdx.y * 32;
    int tx = threadIdx.x, ty = threadIdx.y;
#pragma unroll
    for (int i = 0; i < 32; i += 8)
        s[ty + i][tx] = W[(k0 + ty + i) * 128 + n0 + tx];
    __syncthreads();
#pragma unroll
    for (int i = 0; i < 32; i += 8)
        Wt4[(size_t)(sel * 128 + n0 + ty + i) * 128 + k0 + tx] = s[tx][ty + i];
}
__global__ void tr_sq(const float* __restrict__ W, float* __restrict__ Wt) {
    __shared__ float s[32][33];
    int k0 = blockIdx.x * 32, n0 = blockIdx.y * 32;
    int tx = threadIdx.x, ty = threadIdx.y;
#pragma unroll
    for (int i = 0; i < 32; i += 8)
        s[ty + i][tx] = W[(k0 + ty + i) * 128 + n0 + tx];
    __syncthreads();
#pragma unroll
    for (int i = 0; i < 32; i += 8)
        Wt[(n0 + ty + i) * 128 + k0 + tx] = s[tx][ty + i];
}
__global__ void pack4bias(const float* __restrict__ b0, const float* __restrict__ b1,
                          const float* __restrict__ b2, const float* __restrict__ b3,
                          float* __restrict__ b4) {
    int i = blockIdx.x * blockDim.x + threadIdx.x;
    if (i >= 512) return;
    int sel = i >> 7, j = i & 127;
    b4[i] = (sel == 0) ? b0[j] : (sel == 1) ? b1[j] : (sel == 2) ? b2[j] : b3[j];
}

// ---------------- edge / elementwise kernels ----------------
__global__ void fillk(float* __restrict__ p, int n, float v) {
    int i = blockIdx.x * blockDim.x + threadIdx.x;
    if (i < n) p[i] = v;
}
__global__ void fill2(float* __restrict__ a, float va, float* __restrict__ b, float vb, int n) {
    int i = blockIdx.x * blockDim.x + threadIdx.x;
    if (i < n) { a[i] = va; b[i] = vb; }
}
__global__ void finalize_max(float* __restrict__ p, int n) {
    int i = blockIdx.x * blockDim.x + threadIdx.x;
    if (i < n) { float v = p[i]; if (v < -3.0e38f) p[i] = 0.f; }
}
__global__ void bias_add(float* __restrict__ out, const float* __restrict__ b, int n) {
    int i = blockIdx.x * blockDim.x + threadIdx.x;
    if (i < n) out[i] += b[i & 127];
}
__global__ void copy_slice(const float* __restrict__ qkvs, float* __restrict__ out, int M) {
    int i = blockIdx.x * blockDim.x + threadIdx.x;
    if (i >= M * 32) return;
    int row = i >> 5, c = i & 31;
    *(float4*)&out[(size_t)row * 128 + c * 4] = *(const float4*)&qkvs[(size_t)row * 512 + 384 + c * 4];
}
__global__ void rowdot(const float* __restrict__ X, const float* __restrict__ v,
                       float* __restrict__ out, int M) {
    int w = (blockIdx.x * blockDim.x + threadIdx.x) >> 5;
    int lane = threadIdx.x & 31;
    if (w >= M) return;
    float4 x = *(const float4*)&X[(size_t)w * 128 + lane * 4];
    float4 vv = *(const float4*)&v[lane * 4];
    float p = x.x * vv.x + x.y * vv.y + x.z * vv.z + x.w * vv.w;
#pragma unroll
    for (int o = 16; o; o >>= 1) p += __shfl_xor_sync(0xffffffffu, p, o);
    if (lane == 0) out[w] = p;
}
__global__ void trans_score_k(const float* __restrict__ q, const float* __restrict__ k, int ld,
                              const int* __restrict__ src, const int* __restrict__ dst,
                              float* __restrict__ score, float* __restrict__ nmax, int E) {
    int w = (blockIdx.x * blockDim.x + threadIdx.x) >> 5;
    int lane = threadIdx.x & 31;
    if (w >= E) return;
    int s = src[w], d = dst[w];
    float4 a = *(const float4*)&q[(size_t)d * ld + lane * 4];
    float4 b = *(const float4*)&k[(size_t)s * ld + lane * 4];
    float p = a.x * b.x + a.y * b.y + a.z * b.z + a.w * b.w;
#pragma unroll
    for (int o = 16; o; o >>= 1) p += __shfl_xor_sync(0xffffffffu, p, o);
    if (lane == 0) {
        p *= 0.08838834764831845f;
        score[w] = p;
        atomicMaxF(&nmax[d], p);
    }
}
__global__ void gat_score_k(const float* __restrict__ ssrc, const float* __restrict__ sdst,
                            const int* __restrict__ src, const int* __restrict__ dst,
                            float* __restrict__ score, float* __restrict__ nmax, int E) {
    int e = blockIdx.x * blockDim.x + threadIdx.x;
    if (e >= E) return;
    float s = ssrc[src[e]] + sdst[dst[e]];
    s = (s > 0.f) ? s : 0.2f * s;
    score[e] = s;
    atomicMaxF(&nmax[dst[e]], s);
}
__global__ void expnorm_k(float* __restrict__ score, const int* __restrict__ dst,
                          const float* __restrict__ nmax, float* __restrict__ nsum, int E) {
    int e = blockIdx.x * blockDim.x + threadIdx.x;
    if (e >= E) return;
    int d = dst[e];
    float v = __expf(score[e] - nmax[d]);
    score[e] = v;
    atomicAdd(&nsum[d], v);
}
__global__ void scatter_v4(const float* __restrict__ score, const float* __restrict__ nsum,
                           const float* __restrict__ V, int ldv,
                           const int* __restrict__ src, const int* __restrict__ dst,
                           float* __restrict__ out, int ldo, int E) {
    int w = (blockIdx.x * blockDim.x + threadIdx.x) >> 5;
    int lane = threadIdx.x & 31;
    if (w >= E) return;
    int s = src[w], d = dst[w];
    float a = score[w] / (nsum[d] + 1e-16f);
    float4 v = *(const float4*)&V[(size_t)s * ldv + lane * 4];
    red_add_v4(&out[(size_t)d * ldo + lane * 4], make_float4(a * v.x, a * v.y, a * v.z, a * v.w));
}

// ---------------- host orchestration ----------------
#define GEMM_TF32_SMEM 65536
#define EDGE_TF32_SMEM 98304

struct Scratch {
    float *xL, *xP, *legoA, *pointA, *hs, *A512, *B512;
    float *Wt1c, *Wt1b, *W2t, *Wt4, *b4, *WtG;
    float *esc, *nmax, *nsum, *ssrc, *sdst, *waD;
    int *cnt, *offs;
    int *ll_s, *ll_d, *pp_s, *pp_d, *lp_s, *lp_d, *pl_s, *pl_d;
};

static void sort_edges(const Scratch& S, const int* src, const int* dst, int E, int Nn,
                       int* ss, int* sd) {
    zero_int<<<(Nn + 255) / 256, 256>>>(S.cnt, Nn);
    histo_k<<<(E + 255) / 256, 256>>>(dst, E, S.cnt);
    exscan_k<<<1, 1024>>>(S.cnt, Nn, S.offs);
    sortscat_k<<<(E + 255) / 256, 256>>>(src, dst, E, S.offs, ss, sd);
}

static void trans_conv(const Scratch& S, const float* x, int Nn,
                       const int* src, const int* dst, int E,
                       const float* Wq, const float* bq, const float* Wk, const float* bk,
                       const float* Wv, const float* bv, const float* Ws, const float* bs,
                       float* out) {
    float* qkvs = S.A512;
    tr_pack4<<<dim3(4, 4, 4), dim3(32, 8)>>>(Wq, Wk, Wv, Ws, S.Wt4);
    pack4bias<<<2, 256>>>(bq, bk, bv, bs, S.b4);
    gemm_3xtf32_pipe<<<dim3((Nn + 127) / 128, 4), 256, GEMM_TF32_SMEM>>>(x, S.Wt4, S.b4, qkvs, Nn, 512);
    fill2<<<(Nn + 255) / 256, 256>>>(S.nmax, -INFINITY, S.nsum, 0.f, Nn);
    trans_score_k<<<(E + 7) / 8, 256>>>(qkvs, qkvs + 128, 512, src, dst, S.esc, S.nmax, E);
    expnorm_k<<<(E + 255) / 256, 256>>>(S.esc, dst, S.nmax, S.nsum, E);
    scatter_v4<<<(E + 7) / 8, 256>>>(S.esc, S.nsum, qkvs + 256, 512, src, dst, qkvs + 384, 512, E);
    copy_slice<<<(Nn * 32 + 255) / 256, 256>>>(qkvs, out, Nn);
}

static void gat_conv(const Scratch& S, const float* xs, int Ns, const float* xd, int Nd,
                     const int* src, const int* dst, int E,
                     const float* W, const float* As, const float* Ad, const float* b,
                     float* out) {
    tr_sq<<<dim3(4, 4), dim3(32, 8)>>>(W, S.WtG);
    gemm_3xtf32_pipe<<<dim3((Ns + 127) / 128, 1), 256, GEMM_TF32_SMEM>>>(xs, S.WtG, nullptr, S.hs, Ns, 128);
    rowdot<<<(128 + 7) / 8, 256>>>(W, Ad, S.waD, 128);
    rowdot<<<(Ns + 7) / 8, 256>>>(S.hs, As, S.ssrc, Ns);
    rowdot<<<(Nd + 7) / 8, 256>>>(xd, S.waD, S.sdst, Nd);
    fill2<<<(Nd + 255) / 256, 256>>>(S.nmax, -INFINITY, S.nsum, 0.f, Nd);
    gat_score_k<<<(E + 255) / 256, 256>>>(S.ssrc, S.sdst, src, dst, S.esc, S.nmax, E);
    expnorm_k<<<(E + 255) / 256, 256>>>(S.esc, dst, S.nmax, S.nsum, E);
    scatter_v4<<<(E + 7) / 8, 256>>>(S.esc, S.nsum, S.hs, 128, src, dst, out, 128, E);
    bias_add<<<(Nd * 128 + 255) / 256, 256>>>(out, b, Nd * 128);
}

static void edge_conv(const Scratch& S, const float* x, int Nn,
                      const int* src, const int* dst, int E,
                      const float* W1, const float* b1, const float* W2, const float* b2,
                      float* out) {
    tr_w1<<<dim3(4, 16), dim3(32, 8)>>>(W1, S.Wt1c, S.Wt1b);
    tr_w2<<<dim3(16, 4), dim3(32, 8)>>>(W2, S.W2t);
    gemm_tf32_pipe<<<dim3((Nn + 127) / 128, 4), 256, GEMM_TF32_SMEM>>>(x, S.Wt1c, b1, S.A512, Nn, 512);
    gemm_tf32_pipe<<<dim3((Nn + 127) / 128, 4), 256, GEMM_TF32_SMEM>>>(x, S.Wt1b, nullptr, S.B512, Nn, 512);
    fillk<<<(Nn * 128 + 255) / 256, 256>>>(out, Nn * 128, -INFINITY);
    edge_mlp2_tf32_pipe<<<(E + 127) / 128, 256, EDGE_TF32_SMEM>>>(S.A512, S.B512, src, dst, S.W2t, b2, out, E);
    finalize_max<<<(Nn * 128 + 255) / 256, 256>>>(out, Nn * 128);
}

#define GETSYM(field, symbol) do { void* _p; cudaGetSymbolAddress(&_p, symbol); S.field = (decltype(S.field))_p; } while (0)

extern "C" void kernel_launch(void* const* d_in, const int* in_sizes, int n_in,
                              void* d_out, int out_size) {
    const float* in_xL  = (const float*)d_in[0];
    const float* in_xP  = (const float*)d_in[1];
    const float* tWq = (const float*)d_in[2];
    const float* tbq = (const float*)d_in[3];
    const float* tWk = (const float*)d_in[4];
    const float* tbk = (const float*)d_in[5];
    const float* tWv = (const float*)d_in[6];
    const float* tbv = (const float*)d_in[7];
    const float* tWs = (const float*)d_in[8];
    const float* tbs = (const float*)d_in[9];
    const float* eW1 = (const float*)d_in[10];
    const float* eb1 = (const float*)d_in[11];
    const float* eW2 = (const float*)d_in[12];
    const float* eb2 = (const float*)d_in[13];
    const float* gW  = (const float*)d_in[14];
    const float* gAs = (const float*)d_in[15];
    const float* gAd = (const float*)d_in[16];
    const float* gb  = (const float*)d_in[17];
    const int* ll_src = (const int*)d_in[18];
    const int* ll_dst = (const int*)d_in[19];
    const int* pp_src = (const int*)d_in[20];
    const int* pp_dst = (const int*)d_in[21];
    const int* lp_src = (const int*)d_in[22];
    const int* lp_dst = (const int*)d_in[23];
    const int* pl_src = (const int*)d_in[24];
    const int* pl_dst = (const int*)d_in[25];

    cudaFuncSetAttribute(gemm_tf32_pipe, cudaFuncAttributeMaxDynamicSharedMemorySize, GEMM_TF32_SMEM);
    cudaFuncSetAttribute(gemm_3xtf32_pipe, cudaFuncAttributeMaxDynamicSharedMemorySize, GEMM_TF32_SMEM);
    cudaFuncSetAttribute(edge_mlp2_tf32_pipe, cudaFuncAttributeMaxDynamicSharedMemorySize, EDGE_TF32_SMEM);

    Scratch S;
    GETSYM(xL, g_xL);       GETSYM(xP, g_xP);
    GETSYM(legoA, g_legoA); GETSYM(pointA, g_pointA);
    GETSYM(hs, g_hs);
    GETSYM(A512, g_A512); GETSYM(B512, g_B512);
    GETSYM(Wt1c, g_Wt1c); GETSYM(Wt1b, g_Wt1b); GETSYM(W2t, g_W2t);
    GETSYM(Wt4, g_Wt4); GETSYM(b4, g_b4); GETSYM(WtG, g_WtG);
    GETSYM(esc, g_esc); GETSYM(nmax, g_nmax); GETSYM(nsum, g_nsum);
    GETSYM(ssrc, g_ssrc); GETSYM(sdst, g_sdst); GETSYM(waD, g_waD);
    GETSYM(cnt, g_cnt); GETSYM(offs, g_offs);
    GETSYM(ll_s, g_ll_s); GETSYM(ll_d, g_ll_d);
    GETSYM(pp_s, g_pp_s); GETSYM(pp_d, g_pp_d);
    GETSYM(lp_s, g_lp_s); GETSYM(lp_d, g_lp_d);
    GETSYM(pl_s, g_pl_s); GETSYM(pl_d, g_pl_d);

    cudaMemcpyAsync(S.xL, in_xL, (size_t)NL * DIM * sizeof(float), cudaMemcpyDeviceToDevice);
    cudaMemcpyAsync(S.xP, in_xP, (size_t)NP * DIM * sizeof(float), cudaMemcpyDeviceToDevice);

    // Sort all edge lists by dst once; reused by every conv pass.
    sort_edges(S, ll_src, ll_dst, ELL, NL, S.ll_s, S.ll_d);
    sort_edges(S, pp_src, pp_dst, EPP, NP, S.pp_s, S.pp_d);
    sort_edges(S, lp_src, lp_dst, ELP, NP, S.lp_s, S.lp_d);
    sort_edges(S, pl_src, pl_dst, EPL, NL, S.pl_s, S.pl_d);

    for (int layer = 0; layer < 2; layer++) {
        int iA = 2 * layer, iB = 2 * layer + 1;
        int ilp = 2 * layer, ipl = 2 * layer + 1;

        trans_conv(S, S.xL, NL, S.ll_s, S.ll_d, ELL,
                   tWq + iA * 16384, tbq + iA * 128, tWk + iA * 16384, tbk + iA * 128,
                   tWv + iA * 16384, tbv + iA * 128, tWs + iA * 16384, tbs + iA * 128,
                   S.legoA);
        gat_conv(S, S.xP, NP, S.xL, NL, S.pl_s, S.pl_d, EPL,
                 gW + ipl * 16384, gAs + ipl * 128, gAd + ipl * 128, gb + ipl * 128,
                 S.legoA);
        edge_conv(S, S.xP, NP, S.pp_s, S.pp_d, EPP,
                  eW1 + iA * 131072, eb1 + iA * 512, eW2 + iA * 65536, eb2 + iA * 128,
                  S.pointA);
        gat_conv(S, S.xL, NL, S.xP, NP, S.lp_s, S.lp_d, ELP,
                 gW + ilp * 16384, gAs + ilp * 128, gAd + ilp * 128, gb + ilp * 128,
                 S.pointA);

        trans_conv(S, S.legoA, NL, S.ll_s, S.ll_d, ELL,
                   tWq + iB * 16384, tbq + iB * 128, tWk + iB * 16384, tbk + iB * 128,
                   tWv + iB * 16384, tbv + iB * 128, tWs + iB * 16384, tbs + iB * 128,
                   S.xL);
        edge_conv(S, S.pointA, NP, S.pp_s, S.pp_d, EPP,
                  eW1 + iB * 131072, eb1 + iB * 512, eW2 + iB * 65536, eb2 + iB * 128,
                  S.xP);
    }

    float* out = (float*)d_out;
    cudaMemcpyAsync(out, S.xL, (size_t)NL * DIM * sizeof(float), cudaMemcpyDeviceToDevice);
    cudaMemcpyAsync(out + (size_t)NL * DIM, S.xP, (size_t)NP * DIM * sizeof(float), cudaMemcpyDeviceToDevice);
}

// round 11
// speedup vs baseline: 1.1173x; 1.1173x over previous
#include <cuda_runtime.h>
#include <math.h>
#include <stdint.h>

#define DIM 128
#define NL 50000
#define NP 100000
#define ELL 500000
#define EPP 400000
#define ELP 500000
#define EPL 500000

// ---------------- scratch (device globals; allocation-free rule) ----------------
__device__ __align__(16) float g_xL[NL * DIM];
__device__ __align__(16) float g_xP[NP * DIM];
__device__ __align__(16) float g_legoA[NL * DIM];
__device__ __align__(16) float g_pointA[NP * DIM];
__device__ __align__(16) float g_hs[NP * DIM];
__device__ __align__(16) float g_A512[NP * 512];   // aliased as qkvs[NL*512] (disjoint lifetimes)
__device__ __align__(16) float g_B512[NP * 512];
__device__ __align__(16) float g_Wt1c[512 * 128];
__device__ __align__(16) float g_Wt1b[512 * 128];
__device__ __align__(16) float g_W2t[128 * 512];
__device__ __align__(16) float g_Wt4[512 * 128];
__device__ __align__(16) float g_b4[512];
__device__ __align__(16) float g_WtG[128 * 128];
__device__ __align__(16) float g_esc[500000];
__device__ __align__(16) float g_ssrc[NP];
__device__ __align__(16) float g_sdst[NP];
__device__ __align__(16) float g_waD[DIM];
// sorted edge lists + CSR offsets (built once per launch)
__device__ int g_ll_s[ELL], g_ll_d[ELL];
__device__ int g_lp_s[ELP], g_lp_d[ELP];
__device__ int g_pl_s[EPL], g_pl_d[EPL];
__device__ int g_ll_off[NL + 1];
__device__ int g_lp_off[NP + 1];
__device__ int g_pl_off[NL + 1];
__device__ int g_cnt[NP];
__device__ int g_offs[NP];

// ---------------- small device helpers ----------------
__device__ __forceinline__ void atomicMaxF(float* a, float v) {
    if (v >= 0.f) atomicMax((int*)a, __float_as_int(v));
    else          atomicMin((unsigned int*)a, __float_as_uint(v));
}
__device__ __forceinline__ uint32_t to_tf32(float x) {
    uint32_t r;
    asm("cvt.rna.tf32.f32 %0, %1;" : "=r"(r) : "f"(x));
    return r;
}
__device__ __forceinline__ void ldsm4(uint32_t& r0, uint32_t& r1, uint32_t& r2, uint32_t& r3, uint32_t addr) {
    asm volatile("ldmatrix.sync.aligned.m8n8.x4.shared.b16 {%0,%1,%2,%3}, [%4];"
                 : "=r"(r0), "=r"(r1), "=r"(r2), "=r"(r3) : "r"(addr));
}
__device__ __forceinline__ void mma_tf32(float* c, const uint32_t* a, uint32_t b0, uint32_t b1) {
    asm volatile("mma.sync.aligned.m16n8k8.row.col.f32.tf32.tf32.f32 "
                 "{%0,%1,%2,%3},{%4,%5,%6,%7},{%8,%9},{%0,%1,%2,%3};"
                 : "+f"(c[0]), "+f"(c[1]), "+f"(c[2]), "+f"(c[3])
                 : "r"(a[0]), "r"(a[1]), "r"(a[2]), "r"(a[3]), "r"(b0), "r"(b1));
}
__device__ __forceinline__ void cp_async16(uint32_t saddr, const void* gaddr) {
    asm volatile("cp.async.cg.shared.global [%0], [%1], 16;" :: "r"(saddr), "l"(gaddr));
}
__device__ __forceinline__ void cp_commit() { asm volatile("cp.async.commit_group;"); }
__device__ __forceinline__ void cp_wait1() { asm volatile("cp.async.wait_group 1;" ::: "memory"); }
__device__ __forceinline__ void cp_wait0() { asm volatile("cp.async.wait_group 0;" ::: "memory"); }
__device__ __forceinline__ uint32_t sw_addr(uint32_t base, int r, int g) {
    return base + (uint32_t)((r * 32 + (((g) ^ (r & 7)) << 2)) * 4);
}

// ---------------- edge counting-sort by dst (for CSR segment kernels) ----------------
__global__ void zero_int(int* __restrict__ p, int n) {
    int i = blockIdx.x * blockDim.x + threadIdx.x;
    if (i < n) p[i] = 0;
}
__global__ void histo_k(const int* __restrict__ dst, int E, int* __restrict__ cnt) {
    int e = blockIdx.x * blockDim.x + threadIdx.x;
    if (e < E) atomicAdd(&cnt[dst[e]], 1);
}
__global__ __launch_bounds__(1024) void exscan_k(const int* __restrict__ cnt, int n, int* __restrict__ offs) {
    __shared__ int part[1024];
    int t = threadIdx.x;
    int chunk = (n + 1023) / 1024;
    int begin = t * chunk;
    int end = begin + chunk; if (end > n) end = n; if (begin > n) begin = n;
    int s = 0;
    for (int i = begin; i < end; i++) s += cnt[i];
    part[t] = s;
    __syncthreads();
    for (int off = 1; off < 1024; off <<= 1) {
        int v = (t >= off) ? part[t - off] : 0;
        __syncthreads();
        part[t] += v;
        __syncthreads();
    }
    int base = (t == 0) ? 0 : part[t - 1];
    for (int i = begin; i < end; i++) { offs[i] = base; base += cnt[i]; }
}
__global__ void copy_offs(const int* __restrict__ offs, int n, int E, int* __restrict__ dstoff) {
    int i = blockIdx.x * blockDim.x + threadIdx.x;
    if (i < n) dstoff[i] = offs[i];
    if (i == n) dstoff[n] = E;
}
__global__ void sortscat_k(const int* __restrict__ src, const int* __restrict__ dst, int E,
                           int* __restrict__ offs, int* __restrict__ ss, int* __restrict__ sd) {
    int e = blockIdx.x * blockDim.x + threadIdx.x;
    if (e >= E) return;
    int d = dst[e];
    int p = atomicAdd(&offs[d], 1);
    ss[p] = src[e];
    sd[p] = d;
}

// ---------------- 3xTF32 pipelined node GEMM (fp32-accurate) ----------------
__global__ __launch_bounds__(256) void gemm_3xtf32_pipe(
    const float* __restrict__ X, const float* __restrict__ Wt,
    const float* __restrict__ bias, float* __restrict__ C, int M, int N) {
    extern __shared__ __align__(16) float smemBuf[];
    uint32_t sBase = (uint32_t)__cvta_generic_to_shared(smemBuf);
    int t = threadIdx.x;
    int rowBase = blockIdx.x * 128;
    int colBase = blockIdx.y * 128;
    int warp = t >> 5, lane = t & 31;
    int wm = warp >> 2, wn = warp & 3;
    int mBase = wm * 64, nBase = wn * 32;
    int lr = lane & 15, lh = lane >> 4;

    auto prefetch = [&](int it) {
        int k0 = it * 32;
        uint32_t stg = sBase + (uint32_t)((it & 1) * 32768);
#pragma unroll
        for (int i = 0; i < 4; i++) {
            int c = t + i * 256;
            int r = c >> 3, g = c & 7;
            int row = rowBase + r; if (row >= M) row = M - 1;
            cp_async16(sw_addr(stg, r, g), X + (size_t)row * 128 + k0 + g * 4);
            cp_async16(sw_addr(stg + 16384, r, g), Wt + (size_t)(colBase + r) * 128 + k0 + g * 4);
        }
        cp_commit();
    };

    float acc[4][4][4];
#pragma unroll
    for (int a = 0; a < 4; a++)
#pragma unroll
        for (int b = 0; b < 4; b++)
#pragma unroll
            for (int c = 0; c < 4; c++) acc[a][b][c] = 0.f;

    prefetch(0);
    for (int it = 0; it < 4; it++) {
        if (it + 1 < 4) { prefetch(it + 1); cp_wait1(); } else { cp_wait0(); }
        __syncthreads();
        uint32_t stg = sBase + (uint32_t)((it & 1) * 32768);
#pragma unroll
        for (int ks = 0; ks < 4; ks++) {
            int g = ks * 2 + lh;
            uint32_t ah[4][4], al[4][4], bh[2][4], bl[2][4];
#pragma unroll
            for (int mt = 0; mt < 4; mt++) {
                int row = mBase + mt * 16 + lr;
                uint32_t r0, r1, r2, r3;
                ldsm4(r0, r1, r2, r3, sw_addr(stg, row, g));
                uint32_t raw[4] = {r0, r1, r2, r3};
#pragma unroll
                for (int j = 0; j < 4; j++) {
                    float f = __uint_as_float(raw[j]);
                    uint32_t hi = to_tf32(f);
                    ah[mt][j] = hi;
                    al[mt][j] = to_tf32(f - __uint_as_float(hi));
                }
            }
#pragma unroll
            for (int p = 0; p < 2; p++) {
                int row = nBase + p * 16 + lr;
                uint32_t r0, r1, r2, r3;
                ldsm4(r0, r1, r2, r3, sw_addr(stg + 16384, row, g));
                uint32_t raw[4] = {r0, r1, r2, r3};
#pragma unroll
                for (int j = 0; j < 4; j++) {
                    float f = __uint_as_float(raw[j]);
                    uint32_t hi = to_tf32(f);
                    bh[p][j] = hi;
                    bl[p][j] = to_tf32(f - __uint_as_float(hi));
                }
            }
#pragma unroll
            for (int mt = 0; mt < 4; mt++)
#pragma unroll
                for (int nt = 0; nt < 4; nt++) {
                    int p = nt >> 1, wsel = nt & 1;
                    mma_tf32(acc[mt][nt], al[mt], bh[p][wsel], bh[p][2 + wsel]);
                    mma_tf32(acc[mt][nt], ah[mt], bl[p][wsel], bl[p][2 + wsel]);
                    mma_tf32(acc[mt][nt], ah[mt], bh[p][wsel], bh[p][2 + wsel]);
                }
        }
        __syncthreads();
    }
    int g = lane >> 2, tq = lane & 3;
#pragma unroll
    for (int mt = 0; mt < 4; mt++)
#pragma unroll
        for (int nt = 0; nt < 4; nt++) {
            int col = colBase + nBase + nt * 8 + tq * 2;
            float b0 = bias ? bias[col] : 0.f;
            float b1 = bias ? bias[col + 1] : 0.f;
            int row = rowBase + mBase + mt * 16 + g;
            if (row < M)
                *(float2*)&C[(size_t)row * N + col] = make_float2(acc[mt][nt][0] + b0, acc[mt][nt][1] + b1);
            row += 8;
            if (row < M)
                *(float2*)&C[(size_t)row * N + col] = make_float2(acc[mt][nt][2] + b0, acc[mt][nt][3] + b1);
        }
}

// ---------------- pipelined tf32 node GEMM (single-pass; edge path) ----------------
__global__ __launch_bounds__(256) void gemm_tf32_pipe(
    const float* __restrict__ X, const float* __restrict__ Wt,
    const float* __restrict__ bias, float* __restrict__ C, int M, int N) {
    extern __shared__ __align__(16) float smemBuf[];
    uint32_t sBase = (uint32_t)__cvta_generic_to_shared(smemBuf);
    int t = threadIdx.x;
    int rowBase = blockIdx.x * 128;
    int colBase = blockIdx.y * 128;
    int warp = t >> 5, lane = t & 31;
    int wm = warp >> 2, wn = warp & 3;
    int mBase = wm * 64, nBase = wn * 32;
    int lr = lane & 15, lh = lane >> 4;

    auto prefetch = [&](int it) {
        int k0 = it * 32;
        uint32_t stg = sBase + (uint32_t)((it & 1) * 32768);
#pragma unroll
        for (int i = 0; i < 4; i++) {
            int c = t + i * 256;
            int r = c >> 3, g = c & 7;
            int row = rowBase + r; if (row >= M) row = M - 1;
            cp_async16(sw_addr(stg, r, g), X + (size_t)row * 128 + k0 + g * 4);
            cp_async16(sw_addr(stg + 16384, r, g), Wt + (size_t)(colBase + r) * 128 + k0 + g * 4);
        }
        cp_commit();
    };

    float acc[4][4][4];
#pragma unroll
    for (int a = 0; a < 4; a++)
#pragma unroll
        for (int b = 0; b < 4; b++)
#pragma unroll
            for (int c = 0; c < 4; c++) acc[a][b][c] = 0.f;

    prefetch(0);
    for (int it = 0; it < 4; it++) {
        if (it + 1 < 4) { prefetch(it + 1); cp_wait1(); } else { cp_wait0(); }
        __syncthreads();
        uint32_t stg = sBase + (uint32_t)((it & 1) * 32768);
#pragma unroll
        for (int ks = 0; ks < 4; ks++) {
            int g = ks * 2 + lh;
            uint32_t a[4][4], b[2][4];
#pragma unroll
            for (int mt = 0; mt < 4; mt++) {
                int row = mBase + mt * 16 + lr;
                uint32_t r0, r1, r2, r3;
                ldsm4(r0, r1, r2, r3, sw_addr(stg, row, g));
                a[mt][0] = to_tf32(__uint_as_float(r0));
                a[mt][1] = to_tf32(__uint_as_float(r1));
                a[mt][2] = to_tf32(__uint_as_float(r2));
                a[mt][3] = to_tf32(__uint_as_float(r3));
            }
#pragma unroll
            for (int p = 0; p < 2; p++) {
                int row = nBase + p * 16 + lr;
                uint32_t r0, r1, r2, r3;
                ldsm4(r0, r1, r2, r3, sw_addr(stg + 16384, row, g));
                b[p][0] = to_tf32(__uint_as_float(r0));
                b[p][1] = to_tf32(__uint_as_float(r1));
                b[p][2] = to_tf32(__uint_as_float(r2));
                b[p][3] = to_tf32(__uint_as_float(r3));
            }
#pragma unroll
            for (int mt = 0; mt < 4; mt++)
#pragma unroll
                for (int nt = 0; nt < 4; nt++) {
                    int p = nt >> 1, wsel = nt & 1;
                    mma_tf32(acc[mt][nt], a[mt], b[p][wsel], b[p][2 + wsel]);
                }
        }
        __syncthreads();
    }
    int g = lane >> 2, tq = lane & 3;
#pragma unroll
    for (int mt = 0; mt < 4; mt++)
#pragma unroll
        for (int nt = 0; nt < 4; nt++) {
            int col = colBase + nBase + nt * 8 + tq * 2;
            float b0 = bias ? bias[col] : 0.f;
            float b1 = bias ? bias[col + 1] : 0.f;
            int row = rowBase + mBase + mt * 16 + g;
            if (row < M)
                *(float2*)&C[(size_t)row * N + col] = make_float2(acc[mt][nt][0] + b0, acc[mt][nt][1] + b1);
            row += 8;
            if (row < M)
                *(float2*)&C[(size_t)row * N + col] = make_float2(acc[mt][nt][2] + b0, acc[mt][nt][3] + b1);
        }
}

// ---------------- pipelined tf32 EdgeConv 2nd layer (uses ORIGINAL unsorted edges) ----------------
__global__ __launch_bounds__(256) void edge_mlp2_tf32_pipe(
    const float* __restrict__ Ad, const float* __restrict__ Bs,
    const int* __restrict__ src, const int* __restrict__ dst,
    const float* __restrict__ W2t, const float* __restrict__ b2,
    float* __restrict__ out, int E) {
    extern __shared__ __align__(16) float smemBuf[];
    uint32_t sBase = (uint32_t)__cvta_generic_to_shared(smemBuf);
    __shared__ int sSrc[128], sDst[128];
    int t = threadIdx.x;
    int eBase = blockIdx.x * 128;
    if (t < 128) {
        int e = eBase + t; if (e >= E) e = E - 1;
        sSrc[t] = src[e]; sDst[t] = dst[e];
    }
    __syncthreads();
    int warp = t >> 5, lane = t & 31;
    int wm = warp >> 2, wn = warp & 3;
    int mBase = wm * 64, nBase = wn * 32;
    int lr = lane & 15, lh = lane >> 4;

    auto prefetch = [&](int it) {
        int k0 = it * 32;
        uint32_t stg = sBase + (uint32_t)((it & 1) * 49152);
#pragma unroll
        for (int i = 0; i < 4; i++) {
            int c = t + i * 256;
            int r = c >> 3, g = c & 7;
            uint32_t aAddr = sw_addr(stg, r, g);
            cp_async16(aAddr,         Ad  + (size_t)sDst[r] * 512 + k0 + g * 4);
            cp_async16(aAddr + 16384, Bs  + (size_t)sSrc[r] * 512 + k0 + g * 4);
            cp_async16(aAddr + 32768, W2t + (size_t)r * 512 + k0 + g * 4);
        }
        cp_commit();
    };

    float acc[4][4][4];
#pragma unroll
    for (int a = 0; a < 4; a++)
#pragma unroll
        for (int b = 0; b < 4; b++)
#pragma unroll
            for (int c = 0; c < 4; c++) acc[a][b][c] = 0.f;

    prefetch(0);
    for (int it = 0; it < 16; it++) {
        if (it + 1 < 16) { prefetch(it + 1); cp_wait1(); } else { cp_wait0(); }
        __syncthreads();
        uint32_t stg = sBase + (uint32_t)((it & 1) * 49152);
#pragma unroll
        for (int ks = 0; ks < 4; ks++) {
            int g = ks * 2 + lh;
            uint32_t a[4][4], b[2][4];
#pragma unroll
            for (int mt = 0; mt < 4; mt++) {
                int row = mBase + mt * 16 + lr;
                uint32_t addr = sw_addr(stg, row, g);
                uint32_t a0, a1, a2, a3, c0, c1, c2, c3;
                ldsm4(a0, a1, a2, a3, addr);
                ldsm4(c0, c1, c2, c3, addr + 16384);
                a[mt][0] = to_tf32(fmaxf(__uint_as_float(a0) + __uint_as_float(c0), 0.f));
                a[mt][1] = to_tf32(fmaxf(__uint_as_float(a1) + __uint_as_float(c1), 0.f));
                a[mt][2] = to_tf32(fmaxf(__uint_as_float(a2) + __uint_as_float(c2), 0.f));
                a[mt][3] = to_tf32(fmaxf(__uint_as_float(a3) + __uint_as_float(c3), 0.f));
            }
#pragma unroll
            for (int p = 0; p < 2; p++) {
                int row = nBase + p * 16 + lr;
                uint32_t r0, r1, r2, r3;
                ldsm4(r0, r1, r2, r3, sw_addr(stg + 32768, row, g));
                b[p][0] = to_tf32(__uint_as_float(r0));
                b[p][1] = to_tf32(__uint_as_float(r1));
                b[p][2] = to_tf32(__uint_as_float(r2));
                b[p][3] = to_tf32(__uint_as_float(r3));
            }
#pragma unroll
            for (int mt = 0; mt < 4; mt++)
#pragma unroll
                for (int nt = 0; nt < 4; nt++) {
                    int p = nt >> 1, wsel = nt & 1;
                    mma_tf32(acc[mt][nt], a[mt], b[p][wsel], b[p][2 + wsel]);
                }
        }
        __syncthreads();
    }
    int g = lane >> 2, tq = lane & 3;
#pragma unroll
    for (int mt = 0; mt < 4; mt++)
#pragma unroll
        for (int nt = 0; nt < 4; nt++) {
            int col = nBase + nt * 8 + tq * 2;
            float b0 = b2[col], b1 = b2[col + 1];
            int r = mBase + mt * 16 + g;
            if (eBase + r < E) {
                float* o = &out[(size_t)sDst[r] * 128 + col];
                atomicMaxF(o,     acc[mt][nt][0] + b0);
                atomicMaxF(o + 1, acc[mt][nt][1] + b1);
            }
            r += 8;
            if (eBase + r < E) {
                float* o = &out[(size_t)sDst[r] * 128 + col];
                atomicMaxF(o,     acc[mt][nt][2] + b0);
                atomicMaxF(o + 1, acc[mt][nt][3] + b1);
            }
        }
}

// ---------------- weight packing / transposes ----------------
__global__ void tr_w1(const float* __restrict__ W1, float* __restrict__ WtC, float* __restrict__ WtB) {
    __shared__ float tc[32][33], tb[32][33];
    int k0 = blockIdx.x * 32, n0 = blockIdx.y * 32;
    int tx = threadIdx.x, ty = threadIdx.y;
#pragma unroll
    for (int i = 0; i < 32; i += 8) {
        int k = k0 + ty + i, n = n0 + tx;
        float top = W1[k * 512 + n], bot = W1[(k + 128) * 512 + n];
        tc[ty + i][tx] = top - bot;
        tb[ty + i][tx] = bot;
    }
    __syncthreads();
#pragma unroll
    for (int i = 0; i < 32; i += 8) {
        int n = n0 + ty + i, k = k0 + tx;
        WtC[n * 128 + k] = tc[tx][ty + i];
        WtB[n * 128 + k] = tb[tx][ty + i];
    }
}
__global__ void tr_w2(const float* __restrict__ W2, float* __restrict__ W2t) {
    __shared__ float s[32][33];
    int k0 = blockIdx.x * 32, n0 = blockIdx.y * 32;
    int tx = threadIdx.x, ty = threadIdx.y;
#pragma unroll
    for (int i = 0; i < 32; i += 8)
        s[ty + i][tx] = W2[(k0 + ty + i) * 128 + n0 + tx];
    __syncthreads();
#pragma unroll
    for (int i = 0; i < 32; i += 8)
        W2t[(n0 + ty + i) * 512 + k0 + tx] = s[tx][ty + i];
}
__global__ void tr_pack4(const float* __restrict__ W0, const float* __restrict__ W1,
                         const float* __restrict__ W2, const float* __restrict__ W3,
                         float* __restrict__ Wt4) {
    __shared__ float s[32][33];
    int sel = blockIdx.z;
    const float* W = (sel == 0) ? W0 : (sel == 1) ? W1 : (sel == 2) ? W2 : W3;
    int k0 = blockIdx.x * 32, n0 = blockIdx.y * 32;
    int tx = threadIdx.x, ty = threadIdx.y;
#pragma unroll
    for (int i = 0; i < 32; i += 8)
        s[ty + i][tx] = W[(k0 + ty + i) * 128 + n0 + tx];
    __syncthreads();
#pragma unroll
    for (int i = 0; i < 32; i += 8)
        Wt4[(size_t)(sel * 128 + n0 + ty + i) * 128 + k0 + tx] = s[tx][ty + i];
}
__global__ void tr_sq(const float* __restrict__ W, float* __restrict__ Wt) {
    __shared__ float s[32][33];
    int k0 = blockIdx.x * 32, n0 = blockIdx.y * 32;
    int tx = threadIdx.x, ty = threadIdx.y;
#pragma unroll
    for (int i = 0; i < 32; i += 8)
        s[ty + i][tx] = W[(k0 + ty + i) * 128 + n0 + tx];
    __syncthreads();
#pragma unroll
    for (int i = 0; i < 32; i += 8)
        Wt[(n0 + ty + i) * 128 + k0 + tx] = s[tx][ty + i];
}
__global__ void pack4bias(const float* __restrict__ b0, const float* __restrict__ b1,
                          const float* __restrict__ b2, const float* __restrict__ b3,
                          float* __restrict__ b4) {
    int i = blockIdx.x * blockDim.x + threadIdx.x;
    if (i >= 512) return;
    int sel = i >> 7, j = i & 127;
    b4[i] = (sel == 0) ? b0[j] : (sel == 1) ? b1[j] : (sel == 2) ? b2[j] : b3[j];
}

// ---------------- elementwise / edge kernels ----------------
__global__ void fillk(float* __restrict__ p, int n, float v) {
    int i = blockIdx.x * blockDim.x + threadIdx.x;
    if (i < n) p[i] = v;
}
__global__ void finalize_max(float* __restrict__ p, int n) {
    int i = blockIdx.x * blockDim.x + threadIdx.x;
    if (i < n) { float v = p[i]; if (v < -3.0e38f) p[i] = 0.f; }
}
__global__ void rowdot(const float* __restrict__ X, const float* __restrict__ v,
                       float* __restrict__ out, int M) {
    int w = (blockIdx.x * blockDim.x + threadIdx.x) >> 5;
    int lane = threadIdx.x & 31;
    if (w >= M) return;
    float4 x = *(const float4*)&X[(size_t)w * 128 + lane * 4];
    float4 vv = *(const float4*)&v[lane * 4];
    float p = x.x * vv.x + x.y * vv.y + x.z * vv.z + x.w * vv.w;
#pragma unroll
    for (int o = 16; o; o >>= 1) p += __shfl_xor_sync(0xffffffffu, p, o);
    if (lane == 0) out[w] = p;
}
// Transformer per-edge score into esc (sorted edge order; no atomics).
__global__ void trans_score_k(const float* __restrict__ q, const float* __restrict__ k, int ld,
                              const int* __restrict__ src, const int* __restrict__ dst,
                              float* __restrict__ score, int E) {
    int w = (blockIdx.x * blockDim.x + threadIdx.x) >> 5;
    int lane = threadIdx.x & 31;
    if (w >= E) return;
    int s = src[w], d = dst[w];
    float4 a = *(const float4*)&q[(size_t)d * ld + lane * 4];
    float4 b = *(const float4*)&k[(size_t)s * ld + lane * 4];
    float p = a.x * b.x + a.y * b.y + a.z * b.z + a.w * b.w;
#pragma unroll
    for (int o = 16; o; o >>= 1) p += __shfl_xor_sync(0xffffffffu, p, o);
    if (lane == 0) score[w] = p * 0.08838834764831845f;
}
// CSR segment softmax + aggregate for Transformer: one warp per dst node. No atomics.
// out[d] = skip[d] + sum_e softmax(esc)_e * V[src_e]
__global__ void seg_trans_agg(const float* __restrict__ esc, const int* __restrict__ offs,
                              const int* __restrict__ srcs,
                              const float* __restrict__ V, const float* __restrict__ skip,
                              float* __restrict__ out, int Nd) {
    int w = (blockIdx.x * blockDim.x + threadIdx.x) >> 5;
    int lane = threadIdx.x & 31;
    if (w >= Nd) return;
    int begin = offs[w], end = offs[w + 1];
    float m = -INFINITY;
    for (int i = begin + lane; i < end; i += 32) m = fmaxf(m, esc[i]);
#pragma unroll
    for (int o = 16; o; o >>= 1) m = fmaxf(m, __shfl_xor_sync(0xffffffffu, m, o));
    if (!isfinite(m)) m = 0.f;
    float s = 0.f;
    for (int i = begin + lane; i < end; i += 32) s += __expf(esc[i] - m);
#pragma unroll
    for (int o = 16; o; o >>= 1) s += __shfl_xor_sync(0xffffffffu, s, o);
    float inv = 1.f / (s + 1e-16f);
    float4 acc = make_float4(0.f, 0.f, 0.f, 0.f);
    for (int e = begin; e < end; e++) {
        float wgt = __expf(esc[e] - m) * inv;
        float4 v = *(const float4*)&V[(size_t)srcs[e] * 512 + lane * 4];
        acc.x += wgt * v.x; acc.y += wgt * v.y; acc.z += wgt * v.z; acc.w += wgt * v.w;
    }
    float4 sk = *(const float4*)&skip[(size_t)w * 512 + lane * 4];
    *(float4*)&out[(size_t)w * 128 + lane * 4] =
        make_float4(sk.x + acc.x, sk.y + acc.y, sk.z + acc.z, sk.w + acc.w);
}
// CSR segment softmax + aggregate for GAT: one warp per dst. Scores recomputed from scalars.
// out[d] += sum_e softmax(leaky(ssrc[src_e]+sdst[d]))_e * hs[src_e] + b
__global__ void seg_gat_agg(const int* __restrict__ offs, const int* __restrict__ srcs,
                            const float* __restrict__ ssrc, const float* __restrict__ sdst,
                            const float* __restrict__ hs, const float* __restrict__ b,
                            float* __restrict__ out, int Nd) {
    int w = (blockIdx.x * blockDim.x + threadIdx.x) >> 5;
    int lane = threadIdx.x & 31;
    if (w >= Nd) return;
    int begin = offs[w], end = offs[w + 1];
    float sd = sdst[w];
    float m = -INFINITY;
    for (int i = begin + lane; i < end; i += 32) {
        float sc = ssrc[srcs[i]] + sd;
        sc = (sc > 0.f) ? sc : 0.2f * sc;
        m = fmaxf(m, sc);
    }
#pragma unroll
    for (int o = 16; o; o >>= 1) m = fmaxf(m, __shfl_xor_sync(0xffffffffu, m, o));
    if (!isfinite(m)) m = 0.f;
    float s = 0.f;
    for (int i = begin + lane; i < end; i += 32) {
        float sc = ssrc[srcs[i]] + sd;
        sc = (sc > 0.f) ? sc : 0.2f * sc;
        s += __expf(sc - m);
    }
#pragma unroll
    for (int o = 16; o; o >>= 1) s += __shfl_xor_sync(0xffffffffu, s, o);
    float inv = 1.f / (s + 1e-16f);
    float4 acc = make_float4(0.f, 0.f, 0.f, 0.f);
    for (int e = begin; e < end; e++) {
        int si = srcs[e];
        float sc = ssrc[si] + sd;
        sc = (sc > 0.f) ? sc : 0.2f * sc;
        float wgt = __expf(sc - m) * inv;
        float4 v = *(const float4*)&hs[(size_t)si * 128 + lane * 4];
        acc.x += wgt * v.x; acc.y += wgt * v.y; acc.z += wgt * v.z; acc.w += wgt * v.w;
    }
    float4 bb = *(const float4*)&b[lane * 4];
    float4 cur = *(const float4*)&out[(size_t)w * 128 + lane * 4];
    *(float4*)&out[(size_t)w * 128 + lane * 4] =
        make_float4(cur.x + acc.x + bb.x, cur.y + acc.y + bb.y,
                    cur.z + acc.z + bb.z, cur.w + acc.w + bb.w);
}

// ---------------- host orchestration ----------------
#define GEMM_TF32_SMEM 65536
#define EDGE_TF32_SMEM 98304

struct Scratch {
    float *xL, *xP, *legoA, *pointA, *hs, *A512, *B512;
    float *Wt1c, *Wt1b, *W2t, *Wt4, *b4, *WtG;
    float *esc, *ssrc, *sdst, *waD;
    int *cnt, *offs;
    int *ll_s, *ll_d, *lp_s, *lp_d, *pl_s, *pl_d;
    int *ll_off, *lp_off, *pl_off;
};

static void sort_edges(const Scratch& S, const int* src, const int* dst, int E, int Nn,
                       int* ss, int* sd, int* csr_off) {
    zero_int<<<(Nn + 255) / 256, 256>>>(S.cnt, Nn);
    histo_k<<<(E + 255) / 256, 256>>>(dst, E, S.cnt);
    exscan_k<<<1, 1024>>>(S.cnt, Nn, S.offs);
    copy_offs<<<(Nn + 256) / 256, 256>>>(S.offs, Nn, E, csr_off);
    sortscat_k<<<(E + 255) / 256, 256>>>(src, dst, E, S.offs, ss, sd);
}

static void trans_conv(const Scratch& S, const float* x, int Nn,
                       const int* ssorted, const int* dsorted, const int* csr, int E,
                       const float* Wq, const float* bq, const float* Wk, const float* bk,
                       const float* Wv, const float* bv, const float* Ws, const float* bs,
                       float* out) {
    float* qkvs = S.A512;
    tr_pack4<<<dim3(4, 4, 4), dim3(32, 8)>>>(Wq, Wk, Wv, Ws, S.Wt4);
    pack4bias<<<2, 256>>>(bq, bk, bv, bs, S.b4);
    gemm_3xtf32_pipe<<<dim3((Nn + 127) / 128, 4), 256, GEMM_TF32_SMEM>>>(x, S.Wt4, S.b4, qkvs, Nn, 512);
    trans_score_k<<<(E + 7) / 8, 256>>>(qkvs, qkvs + 128, 512, ssorted, dsorted, S.esc, E);
    seg_trans_agg<<<(Nn * 32 + 255) / 256, 256>>>(S.esc, csr, ssorted, qkvs + 256, qkvs + 384, out, Nn);
}

static void gat_conv(const Scratch& S, const float* xs, int Ns, const float* xd, int Nd,
                     const int* ssorted, const int* csr, int E,
                     const float* W, const float* As, const float* Ad, const float* b,
                     float* out) {
    tr_sq<<<dim3(4, 4), dim3(32, 8)>>>(W, S.WtG);
    gemm_3xtf32_pipe<<<dim3((Ns + 127) / 128, 1), 256, GEMM_TF32_SMEM>>>(xs, S.WtG, nullptr, S.hs, Ns, 128);
    rowdot<<<(128 + 7) / 8, 256>>>(W, Ad, S.waD, 128);
    rowdot<<<(Ns + 7) / 8, 256>>>(S.hs, As, S.ssrc, Ns);
    rowdot<<<(Nd + 7) / 8, 256>>>(xd, S.waD, S.sdst, Nd);
    seg_gat_agg<<<(Nd * 32 + 255) / 256, 256>>>(csr, ssorted, S.ssrc, S.sdst, S.hs, b, out, Nd);
}

static void edge_conv(const Scratch& S, const float* x, int Nn,
                      const int* src, const int* dst, int E,
                      const float* W1, const float* b1, const float* W2, const float* b2,
                      float* out) {
    tr_w1<<<dim3(4, 16), dim3(32, 8)>>>(W1, S.Wt1c, S.Wt1b);
    tr_w2<<<dim3(16, 4), dim3(32, 8)>>>(W2, S.W2t);
    gemm_tf32_pipe<<<dim3((Nn + 127) / 128, 4), 256, GEMM_TF32_SMEM>>>(x, S.Wt1c, b1, S.A512, Nn, 512);
    gemm_tf32_pipe<<<dim3((Nn + 127) / 128, 4), 256, GEMM_TF32_SMEM>>>(x, S.Wt1b, nullptr, S.B512, Nn, 512);
    fillk<<<(Nn * 128 + 255) / 256, 256>>>(out, Nn * 128, -INFINITY);
    edge_mlp2_tf32_pipe<<<(E + 127) / 128, 256, EDGE_TF32_SMEM>>>(S.A512, S.B512, src, dst, S.W2t, b2, out, E);
    finalize_max<<<(Nn * 128 + 255) / 256, 256>>>(out, Nn * 128);
}

#define GETSYM(field, symbol) do { void* _p; cudaGetSymbolAddress(&_p, symbol); S.field = (decltype(S.field))_p; } while (0)

extern "C" void kernel_launch(void* const* d_in, const int* in_sizes, int n_in,
                              void* d_out, int out_size) {
    const float* in_xL  = (const float*)d_in[0];
    const float* in_xP  = (const float*)d_in[1];
    const float* tWq = (const float*)d_in[2];
    const float* tbq = (const float*)d_in[3];
    const float* tWk = (const float*)d_in[4];
    const float* tbk = (const float*)d_in[5];
    const float* tWv = (const float*)d_in[6];
    const float* tbv = (const float*)d_in[7];
    const float* tWs = (const float*)d_in[8];
    const float* tbs = (const float*)d_in[9];
    const float* eW1 = (const float*)d_in[10];
    const float* eb1 = (const float*)d_in[11];
    const float* eW2 = (const float*)d_in[12];
    const float* eb2 = (const float*)d_in[13];
    const float* gW  = (const float*)d_in[14];
    const float* gAs = (const float*)d_in[15];
    const float* gAd = (const float*)d_in[16];
    const float* gb  = (const float*)d_in[17];
    const int* ll_src = (const int*)d_in[18];
    const int* ll_dst = (const int*)d_in[19];
    const int* pp_src = (const int*)d_in[20];
    const int* pp_dst = (const int*)d_in[21];
    const int* lp_src = (const int*)d_in[22];
    const int* lp_dst = (const int*)d_in[23];
    const int* pl_src = (const int*)d_in[24];
    const int* pl_dst = (const int*)d_in[25];

    cudaFuncSetAttribute(gemm_tf32_pipe, cudaFuncAttributeMaxDynamicSharedMemorySize, GEMM_TF32_SMEM);
    cudaFuncSetAttribute(gemm_3xtf32_pipe, cudaFuncAttributeMaxDynamicSharedMemorySize, GEMM_TF32_SMEM);
    cudaFuncSetAttribute(edge_mlp2_tf32_pipe, cudaFuncAttributeMaxDynamicSharedMemorySize, EDGE_TF32_SMEM);

    Scratch S;
    GETSYM(xL, g_xL);       GETSYM(xP, g_xP);
    GETSYM(legoA, g_legoA); GETSYM(pointA, g_pointA);
    GETSYM(hs, g_hs);
    GETSYM(A512, g_A512); GETSYM(B512, g_B512);
    GETSYM(Wt1c, g_Wt1c); GETSYM(Wt1b, g_Wt1b); GETSYM(W2t, g_W2t);
    GETSYM(Wt4, g_Wt4); GETSYM(b4, g_b4); GETSYM(WtG, g_WtG);
    GETSYM(esc, g_esc);
    GETSYM(ssrc, g_ssrc); GETSYM(sdst, g_sdst); GETSYM(waD, g_waD);
    GETSYM(cnt, g_cnt); GETSYM(offs, g_offs);
    GETSYM(ll_s, g_ll_s); GETSYM(ll_d, g_ll_d);
    GETSYM(lp_s, g_lp_s); GETSYM(lp_d, g_lp_d);
    GETSYM(pl_s, g_pl_s); GETSYM(pl_d, g_pl_d);
    GETSYM(ll_off, g_ll_off); GETSYM(lp_off, g_lp_off); GETSYM(pl_off, g_pl_off);

    cudaMemcpyAsync(S.xL, in_xL, (size_t)NL * DIM * sizeof(float), cudaMemcpyDeviceToDevice);
    cudaMemcpyAsync(S.xP, in_xP, (size_t)NP * DIM * sizeof(float), cudaMemcpyDeviceToDevice);

    // Sort + CSR for segment kernels (trans/gat only; edge_conv keeps original order).
    sort_edges(S, ll_src, ll_dst, ELL, NL, S.ll_s, S.ll_d, S.ll_off);
    sort_edges(S, lp_src, lp_dst, ELP, NP, S.lp_s, S.lp_d, S.lp_off);
    sort_edges(S, pl_src, pl_dst, EPL, NL, S.pl_s, S.pl_d, S.pl_off);

    for (int layer = 0; layer < 2; layer++) {
        int iA = 2 * layer, iB = 2 * layer + 1;
        int ilp = 2 * layer, ipl = 2 * layer + 1;

        trans_conv(S, S.xL, NL, S.ll_s, S.ll_d, S.ll_off, ELL,
                   tWq + iA * 16384, tbq + iA * 128, tWk + iA * 16384, tbk + iA * 128,
                   tWv + iA * 16384, tbv + iA * 128, tWs + iA * 16384, tbs + iA * 128,
                   S.legoA);
        gat_conv(S, S.xP, NP, S.xL, NL, S.pl_s, S.pl_off, EPL,
                 gW + ipl * 16384, gAs + ipl * 128, gAd + ipl * 128, gb + ipl * 128,
                 S.legoA);
        edge_conv(S, S.xP, NP, pp_src, pp_dst, EPP,
                  eW1 + iA * 131072, eb1 + iA * 512, eW2 + iA * 65536, eb2 + iA * 128,
                  S.pointA);
        gat_conv(S, S.xL, NL, S.xP, NP, S.lp_s, S.lp_off, ELP,
                 gW + ilp * 16384, gAs + ilp * 128, gAd + ilp * 128, gb + ilp * 128,
                 S.pointA);

        trans_conv(S, S.legoA, NL, S.ll_s, S.ll_d, S.ll_off, ELL,
                   tWq + iB * 16384, tbq + iB * 128, tWk + iB * 16384, tbk + iB * 128,
                   tWv + iB * 16384, tbv + iB * 128, tWs + iB * 16384, tbs + iB * 128,
                   S.xL);
        edge_conv(S, S.pointA, NP, pp_src, pp_dst, EPP,
                  eW1 + iB * 131072, eb1 + iB * 512, eW2 + iB * 65536, eb2 + iB * 128,
                  S.xP);
    }

    float* out = (float*)d_out;
    cudaMemcpyAsync(out, S.xL, (size_t)NL * DIM * sizeof(float), cudaMemcpyDeviceToDevice);
    cudaMemcpyAsync(out + (size_t)NL * DIM, S.xP, (size_t)NP * DIM * sizeof(float), cudaMemcpyDeviceToDevice);
}